// round 2
// baseline (speedup 1.0000x reference)
#include <cuda_runtime.h>
#include <cuda_bf16.h>
#include <cstdint>

// Problem constants
#define B_  2
#define T_  2048
#define D_  1024
#define H_  16
#define DH_ 64
#define TOPK_ 32
#define BH_ (B_*H_)

// ---------------------------------------------------------------------------
// Scratch (static device globals; no allocation allowed)
// ---------------------------------------------------------------------------
__device__ __align__(16) float g_Q[(size_t)BH_ * T_ * DH_];   // [BH,T,DH]
__device__ __align__(16) float g_K[(size_t)BH_ * T_ * DH_];
__device__ __align__(16) float g_V[(size_t)BH_ * T_ * DH_];
__device__ __align__(16) float g_Qt[(size_t)BH_ * DH_ * T_];  // [BH,DH,T]
__device__ __align__(16) float g_Kt[(size_t)BH_ * DH_ * T_];
__device__ __align__(16) float g_AO[(size_t)B_ * T_ * D_];    // attn out [B,T,D]

// ---------------------------------------------------------------------------
// Generic C = A @ B^T GEMM, 128x128x16 tile, 256 threads, 8x8 micro-tile.
// ---------------------------------------------------------------------------
#define EPI_PLAIN 0
#define EPI_BIAS  1
#define EPI_HEADS 2

template<int EPI>
__global__ __launch_bounds__(256)
void gemm_abt(const float* __restrict__ A, const float* __restrict__ Bm,
              const float* __restrict__ bias, float* __restrict__ C,
              int M, int N, int K)
{
    __shared__ float AsT[16][128];
    __shared__ float BsT[16][128];

    const int tid = threadIdx.x;
    const int tx = tid & 15;
    const int ty = tid >> 4;
    const int m0 = blockIdx.y * 128;
    const int n0 = blockIdx.x * 128;

    float acc[8][8];
#pragma unroll
    for (int i = 0; i < 8; i++)
#pragma unroll
        for (int j = 0; j < 8; j++) acc[i][j] = 0.f;

    for (int k0 = 0; k0 < K; k0 += 16) {
#pragma unroll
        for (int i = 0; i < 2; i++) {
            int idx  = tid * 2 + i;
            int row  = idx >> 2;
            int col4 = (idx & 3) * 4;
            float4 va = *(const float4*)(A + (long)(m0 + row) * K + k0 + col4);
            AsT[col4 + 0][row] = va.x;
            AsT[col4 + 1][row] = va.y;
            AsT[col4 + 2][row] = va.z;
            AsT[col4 + 3][row] = va.w;
            float4 vb = *(const float4*)(Bm + (long)(n0 + row) * K + k0 + col4);
            BsT[col4 + 0][row] = vb.x;
            BsT[col4 + 1][row] = vb.y;
            BsT[col4 + 2][row] = vb.z;
            BsT[col4 + 3][row] = vb.w;
        }
        __syncthreads();
#pragma unroll
        for (int k = 0; k < 16; k++) {
            float a[8], b[8];
            *(float4*)&a[0] = *(const float4*)&AsT[k][ty * 8];
            *(float4*)&a[4] = *(const float4*)&AsT[k][ty * 8 + 4];
            *(float4*)&b[0] = *(const float4*)&BsT[k][tx * 8];
            *(float4*)&b[4] = *(const float4*)&BsT[k][tx * 8 + 4];
#pragma unroll
            for (int i = 0; i < 8; i++)
#pragma unroll
                for (int j = 0; j < 8; j++)
                    acc[i][j] += a[i] * b[j];
        }
        __syncthreads();
    }

#pragma unroll
    for (int i = 0; i < 8; i++) {
        int m = m0 + ty * 8 + i;
#pragma unroll
        for (int j = 0; j < 8; j += 4) {
            int n = n0 + tx * 8 + j;
            float4 r = make_float4(acc[i][j], acc[i][j + 1], acc[i][j + 2], acc[i][j + 3]);
            if (EPI == EPI_PLAIN) {
                *(float4*)(C + (long)m * N + n) = r;
            } else if (EPI == EPI_BIAS) {
                r.x += bias[n]; r.y += bias[n + 1]; r.z += bias[n + 2]; r.w += bias[n + 3];
                *(float4*)(C + (long)m * N + n) = r;
            } else { // EPI_HEADS: N==1024, write [BH,T,DH]
                int bb = m >> 11, t = m & (T_ - 1);
                int h = n >> 6, inner = n & (DH_ - 1);
                float* dst = C + (((long)(bb * H_ + h) * T_ + t) * DH_ + inner);
                *(float4*)dst = r;
            }
        }
    }
}

// ---------------------------------------------------------------------------
// Transpose [BH,T,DH] -> [BH,DH,T]  (32x32 tiles)
// ---------------------------------------------------------------------------
__global__ __launch_bounds__(256)
void transpose_qk(const float* __restrict__ in, float* __restrict__ outp)
{
    __shared__ float tile[32][33];
    const int bh = blockIdx.z;
    const int t0 = blockIdx.x * 32;
    const int d0 = blockIdx.y * 32;
    const float* ib = in + (long)bh * T_ * DH_;
    float* ob = outp + (long)bh * DH_ * T_;
    const int x = threadIdx.x & 31;
    const int y = threadIdx.x >> 5;   // 0..7
#pragma unroll
    for (int i = 0; i < 32; i += 8)
        tile[y + i][x] = ib[(long)(t0 + y + i) * DH_ + d0 + x];
    __syncthreads();
#pragma unroll
    for (int i = 0; i < 32; i += 8)
        ob[(long)(d0 + y + i) * T_ + t0 + x] = tile[x][y + i];
}

// ---------------------------------------------------------------------------
// Fused scores + exact top-32 + softmax + AV.
// One CTA per (bh, 128-query tile). 256 threads.
// Qt/Kt: [BH][DH][T] fp32, V: [BH][T][DH], O: [B,T,D]
// ---------------------------------------------------------------------------
#define SC(r,c)   Sc[(r)*133 + (c)]
#define SV(r,e)   svals[(r)*33 + (e)]
#define SI(r,e)   sidx[(r)*33 + (e)]

#define FUSED_SMEM ((64*128 + 64*128 + 128*133 + 128*33)*4 + 128*33*4 + 128*4)

__global__ __launch_bounds__(256)
void fused_attn(const float* __restrict__ Qt, const float* __restrict__ Kt,
                const float* __restrict__ V, float* __restrict__ O)
{
    extern __shared__ char smem_raw[];
    float* QsT   = (float*)smem_raw;             // [64][128]
    float* KsT   = QsT + 64 * 128;               // [64][128]
    float* Sc    = KsT + 64 * 128;               // [128][133]
    float* svals = Sc + 128 * 133;               // [128][33]
    int*   sidx  = (int*)(svals + 128 * 33);     // [128][33]
    float* sinv  = (float*)(sidx + 128 * 33);    // [128]

    const int tid = threadIdx.x;
    const int tx = tid & 15;
    const int ty = tid >> 4;
    const int bh = blockIdx.y;
    const int q0 = blockIdx.x * 128;
    const float* Qtb = Qt + (long)bh * DH_ * T_;
    const float* Ktb = Kt + (long)bh * DH_ * T_;

    // Load Q tile: QsT[dh][0..127]
#pragma unroll
    for (int i = 0; i < 8; i++) {
        int lin = tid + i * 256;
        int dh = lin >> 5;
        int c4 = (lin & 31) * 4;
        *(float4*)&QsT[dh * 128 + c4] = *(const float4*)(Qtb + (long)dh * T_ + q0 + c4);
    }

    // Per-row top-32 selection state (owner threads 0..127)
    float vmin = 0.f;
    int mslot = 0, cnt = 0;

    for (int ch = 0; ch < 16; ch++) {
        const int k0 = ch * 128;
        __syncthreads();   // prev GEMM KsT reads + prev selection Sc reads done
#pragma unroll
        for (int i = 0; i < 8; i++) {
            int lin = tid + i * 256;
            int dh = lin >> 5;
            int c4 = (lin & 31) * 4;
            *(float4*)&KsT[dh * 128 + c4] = *(const float4*)(Ktb + (long)dh * T_ + k0 + c4);
        }
        __syncthreads();

        float acc[8][8];
#pragma unroll
        for (int i = 0; i < 8; i++)
#pragma unroll
            for (int j = 0; j < 8; j++) acc[i][j] = 0.f;

#pragma unroll 16
        for (int k = 0; k < 64; k++) {
            float a[8], b[8];
            *(float4*)&a[0] = *(const float4*)&QsT[k * 128 + ty * 8];
            *(float4*)&a[4] = *(const float4*)&QsT[k * 128 + ty * 8 + 4];
            *(float4*)&b[0] = *(const float4*)&KsT[k * 128 + tx * 8];
            *(float4*)&b[4] = *(const float4*)&KsT[k * 128 + tx * 8 + 4];
#pragma unroll
            for (int i = 0; i < 8; i++)
#pragma unroll
                for (int j = 0; j < 8; j++)
                    acc[i][j] += a[i] * b[j];
        }

        // stage scaled scores (bank-rotated scalar stores)
#pragma unroll
        for (int i = 0; i < 8; i++) {
            int row = ty * 8 + i;
#pragma unroll
            for (int j = 0; j < 8; j++) {
                int jj = (j + tx) & 7;
                SC(row, tx * 8 + jj) = acc[i][jj] * 0.125f;
            }
        }
        __syncthreads();

        // exact top-32 maintenance, one owner thread per row
        if (tid < 128) {
            const int r = tid;
            for (int j = 0; j < 128; j++) {
                float s = SC(r, j);
                if (cnt < 32) {
                    if (cnt == 0 || s < vmin) { vmin = s; mslot = cnt; }
                    SV(r, cnt) = s; SI(r, cnt) = k0 + j; cnt++;
                } else if (s > vmin) {
                    SV(r, mslot) = s; SI(r, mslot) = k0 + j;
                    vmin = SV(r, 0); mslot = 0;
#pragma unroll
                    for (int e = 1; e < 32; e++) {
                        float v = SV(r, e);
                        if (v < vmin) { vmin = v; mslot = e; }
                    }
                }
            }
        }
    }

    // softmax over survivors (owner threads)
    if (tid < 128) {
        const int r = tid;
        float m = SV(r, 0);
#pragma unroll
        for (int e = 1; e < 32; e++) m = fmaxf(m, SV(r, e));
        float sum = 0.f;
#pragma unroll
        for (int e = 0; e < 32; e++) {
            float p = __expf(SV(r, e) - m);
            SV(r, e) = p;
            sum += p;
        }
        sinv[r] = 1.f / sum;
    }
    __syncthreads();

    // sparse P @ V : warp w handles rows 16w..16w+15, lane owns dims 2l,2l+1
    const int warp = tid >> 5, lane = tid & 31;
    const float* Vb = V + (long)bh * T_ * DH_;
    const int bb = bh >> 4, h = bh & (H_ - 1);
    for (int rr = 0; rr < 16; rr++) {
        const int r = warp * 16 + rr;
        const float inv = sinv[r];
        float a0 = 0.f, a1 = 0.f;
#pragma unroll 4
        for (int e = 0; e < 32; e++) {
            float p = SV(r, e);
            int ki = SI(r, e);
            float2 v = *(const float2*)(Vb + (long)ki * DH_ + lane * 2);
            a0 += p * v.x;
            a1 += p * v.y;
        }
        float2 o = make_float2(a0 * inv, a1 * inv);
        *(float2*)(O + ((long)(bb * T_ + q0 + r)) * D_ + h * DH_ + lane * 2) = o;
    }
}

// ---------------------------------------------------------------------------
// Launch
// ---------------------------------------------------------------------------
extern "C" void kernel_launch(void* const* d_in, const int* in_sizes, int n_in,
                              void* d_out, int out_size)
{
    const float* x    = (const float*)d_in[0];
    const float* Wq   = (const float*)d_in[1];
    const float* Wk   = (const float*)d_in[2];
    const float* Wv   = (const float*)d_in[3];
    const float* Wo_w = (const float*)d_in[4];
    const float* Wo_b = (const float*)d_in[5];
    float* out = (float*)d_out;

    float *pQ, *pK, *pV, *pQt, *pKt, *pAO;
    cudaGetSymbolAddress((void**)&pQ,  g_Q);
    cudaGetSymbolAddress((void**)&pK,  g_K);
    cudaGetSymbolAddress((void**)&pV,  g_V);
    cudaGetSymbolAddress((void**)&pQt, g_Qt);
    cudaGetSymbolAddress((void**)&pKt, g_Kt);
    cudaGetSymbolAddress((void**)&pAO, g_AO);

    const int M = B_ * T_;   // 4096

    // 1) QKV projections (head-split epilogue)
    {
        dim3 grid(D_ / 128, M / 128, 1);
        gemm_abt<EPI_HEADS><<<grid, 256>>>(x, Wq, nullptr, pQ, M, D_, D_);
        gemm_abt<EPI_HEADS><<<grid, 256>>>(x, Wk, nullptr, pK, M, D_, D_);
        gemm_abt<EPI_HEADS><<<grid, 256>>>(x, Wv, nullptr, pV, M, D_, D_);
    }

    // 2) Transpose Q,K -> [BH,DH,T]
    {
        dim3 grid(T_ / 32, DH_ / 32, BH_);
        transpose_qk<<<grid, 256>>>(pQ, pQt);
        transpose_qk<<<grid, 256>>>(pK, pKt);
    }

    // 3) Fused scores + top-32 + softmax + AV -> g_AO [B,T,D]
    {
        cudaFuncSetAttribute(fused_attn, cudaFuncAttributeMaxDynamicSharedMemorySize,
                             FUSED_SMEM);
        dim3 grid(T_ / 128, BH_, 1);   // 16 x 32 = 512 CTAs
        fused_attn<<<grid, 256, FUSED_SMEM>>>(pQt, pKt, pV, pAO);
    }

    // 4) Output projection with bias -> d_out
    {
        dim3 grid(D_ / 128, M / 128, 1);
        gemm_abt<EPI_BIAS><<<grid, 256>>>(pAO, Wo_w, Wo_b, out, M, D_, D_);
    }
}

// round 4
// speedup vs baseline: 1.5748x; 1.5748x over previous
#include <cuda_runtime.h>
#include <cuda_bf16.h>
#include <cstdint>

// Problem constants
#define B_  2
#define T_  2048
#define D_  1024
#define H_  16
#define DH_ 64
#define TOPK_ 32
#define BH_ (B_*H_)

// ---------------------------------------------------------------------------
// Scratch (static device globals; no allocation allowed)
// ---------------------------------------------------------------------------
__device__ __align__(16) float g_Q[(size_t)BH_ * T_ * DH_];   // [BH,T,DH]
__device__ __align__(16) float g_K[(size_t)BH_ * T_ * DH_];
__device__ __align__(16) float g_V[(size_t)BH_ * T_ * DH_];
__device__ __align__(16) float g_S[(size_t)BH_ * T_ * T_];    // [BH,T,T] scores
__device__ __align__(16) float g_AO[(size_t)B_ * T_ * D_];    // attn out [B,T,D]

// ---------------------------------------------------------------------------
// Generic C = A @ B^T GEMM, 128x128x16 tile, 256 threads, 8x8 micro-tile.
// ---------------------------------------------------------------------------
#define EPI_PLAIN 0
#define EPI_BIAS  1
#define EPI_HEADS 2
#define EPI_SCALE 3

template<int EPI>
__global__ __launch_bounds__(256)
void gemm_abt(const float* __restrict__ A, const float* __restrict__ Bm,
              const float* __restrict__ bias, float* __restrict__ C,
              int M, int N, int K,
              long strideA, long strideB, long strideC)
{
    const float* Ab = A + (long)blockIdx.z * strideA;
    const float* Bb = Bm + (long)blockIdx.z * strideB;
    float* Cb = C + (long)blockIdx.z * strideC;

    __shared__ float AsT[16][128];
    __shared__ float BsT[16][128];

    const int tid = threadIdx.x;
    const int tx = tid & 15;
    const int ty = tid >> 4;
    const int m0 = blockIdx.y * 128;
    const int n0 = blockIdx.x * 128;

    float acc[8][8];
#pragma unroll
    for (int i = 0; i < 8; i++)
#pragma unroll
        for (int j = 0; j < 8; j++) acc[i][j] = 0.f;

    for (int k0 = 0; k0 < K; k0 += 16) {
#pragma unroll
        for (int i = 0; i < 2; i++) {
            int idx  = tid * 2 + i;
            int row  = idx >> 2;
            int col4 = (idx & 3) * 4;
            float4 va = *(const float4*)(Ab + (long)(m0 + row) * K + k0 + col4);
            AsT[col4 + 0][row] = va.x;
            AsT[col4 + 1][row] = va.y;
            AsT[col4 + 2][row] = va.z;
            AsT[col4 + 3][row] = va.w;
            float4 vb = *(const float4*)(Bb + (long)(n0 + row) * K + k0 + col4);
            BsT[col4 + 0][row] = vb.x;
            BsT[col4 + 1][row] = vb.y;
            BsT[col4 + 2][row] = vb.z;
            BsT[col4 + 3][row] = vb.w;
        }
        __syncthreads();
#pragma unroll
        for (int k = 0; k < 16; k++) {
            float a[8], b[8];
            *(float4*)&a[0] = *(const float4*)&AsT[k][ty * 8];
            *(float4*)&a[4] = *(const float4*)&AsT[k][ty * 8 + 4];
            *(float4*)&b[0] = *(const float4*)&BsT[k][tx * 8];
            *(float4*)&b[4] = *(const float4*)&BsT[k][tx * 8 + 4];
#pragma unroll
            for (int i = 0; i < 8; i++)
#pragma unroll
                for (int j = 0; j < 8; j++)
                    acc[i][j] += a[i] * b[j];
        }
        __syncthreads();
    }

#pragma unroll
    for (int i = 0; i < 8; i++) {
        int m = m0 + ty * 8 + i;
#pragma unroll
        for (int j = 0; j < 8; j += 4) {
            int n = n0 + tx * 8 + j;
            float4 r = make_float4(acc[i][j], acc[i][j + 1], acc[i][j + 2], acc[i][j + 3]);
            if (EPI == EPI_PLAIN) {
                *(float4*)(Cb + (long)m * N + n) = r;
            } else if (EPI == EPI_BIAS) {
                r.x += bias[n]; r.y += bias[n + 1]; r.z += bias[n + 2]; r.w += bias[n + 3];
                *(float4*)(Cb + (long)m * N + n) = r;
            } else if (EPI == EPI_SCALE) {
                r.x *= 0.125f; r.y *= 0.125f; r.z *= 0.125f; r.w *= 0.125f;
                *(float4*)(Cb + (long)m * N + n) = r;
            } else { // EPI_HEADS: N==1024, write [BH,T,DH]
                int bb = m >> 11, t = m & (T_ - 1);
                int h = n >> 6, inner = n & (DH_ - 1);
                float* dst = Cb + (((long)(bb * H_ + h) * T_ + t) * DH_ + inner);
                *(float4*)dst = r;
            }
        }
    }
}

// ---------------------------------------------------------------------------
// Top-k threshold via 4-level radix select (exact kth largest in monotone
// uint domain), softmax over survivors, sparse P@V.
// One block (128 threads) per query row.
// ---------------------------------------------------------------------------
__device__ __forceinline__ unsigned uencode(float f) {
    unsigned b = __float_as_uint(f);
    return (b & 0x80000000u) ? ~b : (b | 0x80000000u);
}
__device__ __forceinline__ float udecode(unsigned u) {
    unsigned b = (u & 0x80000000u) ? (u & 0x7fffffffu) : ~u;
    return __uint_as_float(b);
}

__global__ __launch_bounds__(128)
void topk_softmax_av(const float* __restrict__ S, const float* __restrict__ V,
                     float* __restrict__ O)
{
    __shared__ int      hist[256];
    __shared__ int      s_list[128];
    __shared__ float    s_s[128];       // raw scores of survivors -> probs
    __shared__ float    s_part[128];    // AV partials [half][64]
    __shared__ unsigned s_prefix;
    __shared__ int      s_kp;
    __shared__ int      s_cnt;
    __shared__ float    s_inv;

    const long row = blockIdx.x;            // bh*T + tq
    const int bh = (int)(row >> 11);
    const int tq = (int)(row & (T_ - 1));
    const float* Srow = S + row * T_;
    const int tid = threadIdx.x;

    if (tid == 0) s_cnt = 0;

    // Load 16 scores/thread (coalesced), encode to ordered uints in registers
    unsigned uloc[16];
#pragma unroll
    for (int i = 0; i < 16; i++)
        uloc[i] = uencode(Srow[tid + i * 128]);

    // ---- 4-level radix select: find exact 32nd-largest encoded value ----
    unsigned prefix = 0;
    int kprime = TOPK_;
#pragma unroll
    for (int level = 3; level >= 0; --level) {
        const int sh = level * 8;
        // clear histogram
        hist[tid] = 0;
        hist[tid + 128] = 0;
        __syncthreads();
        // histogram current byte of values matching prefix in higher bytes
        if (level == 3) {
#pragma unroll
            for (int i = 0; i < 16; i++)
                atomicAdd(&hist[uloc[i] >> 24], 1);
        } else {
            const unsigned hip = prefix >> (sh + 8);
#pragma unroll
            for (int i = 0; i < 16; i++) {
                unsigned u = uloc[i];
                if ((u >> (sh + 8)) == hip)
                    atomicAdd(&hist[(u >> sh) & 0xFFu], 1);
            }
        }
        __syncthreads();
        // warp 0: suffix-scan 32 groups of 8 bins, pick bin
        if (tid < 32) {
            const int base = tid * 8;
            int s = 0;
#pragma unroll
            for (int j = 0; j < 8; j++) s += hist[base + j];
            int suf = s;
#pragma unroll
            for (int off = 1; off < 32; off <<= 1) {
                int o = __shfl_down_sync(0xffffffffu, suf, off);
                if (tid + off < 32) suf += o;
            }
            int sufnext = __shfl_down_sync(0xffffffffu, suf, 1);
            if (tid == 31) sufnext = 0;
            unsigned mk = __ballot_sync(0xffffffffu, suf >= kprime);
            int lsel = 31 - __clz(mk);
            if (tid == lsel) {
                int running = sufnext;   // count of values in bins above
                int b = base + 7;
                for (; b >= base; --b) {
                    int h = hist[b];
                    if (running + h >= kprime) break;
                    running += h;
                }
                s_prefix = prefix | ((unsigned)b << sh);
                s_kp = kprime - running;
            }
        }
        __syncthreads();
        prefix = s_prefix;
        kprime = s_kp;
    }
    const unsigned uthr = prefix;

    // ---- compact survivors (>= threshold keeps ties, matching reference) --
#pragma unroll
    for (int i = 0; i < 16; i++) {
        unsigned u = uloc[i];
        if (u >= uthr) {
            int pos = atomicAdd(&s_cnt, 1);
            if (pos < 128) {
                s_list[pos] = tid + i * 128;
                s_s[pos] = udecode(u);
            }
        }
    }
    __syncthreads();
    const int cnt = min(s_cnt, 128);

    // ---- softmax over survivors (warp 0) ----
    if (tid < 32) {
        float m = -3.4e38f;
        for (int e = tid; e < cnt; e += 32) m = fmaxf(m, s_s[e]);
#pragma unroll
        for (int off = 16; off; off >>= 1)
            m = fmaxf(m, __shfl_xor_sync(0xffffffffu, m, off));
        float sum = 0.f;
        for (int e = tid; e < cnt; e += 32) {
            float p = __expf(s_s[e] - m);
            s_s[e] = p;
            sum += p;
        }
#pragma unroll
        for (int off = 16; off; off >>= 1)
            sum += __shfl_xor_sync(0xffffffffu, sum, off);
        if (tid == 0) s_inv = 1.f / sum;
    }
    __syncthreads();

    // ---- sparse P @ V : all 128 threads (2 partials per output dim) ----
    {
        const int dim = tid & 63;
        const int half = tid >> 6;
        const float* Vb = V + (long)bh * T_ * DH_;
        float acc = 0.f;
        for (int e = half; e < cnt; e += 2)
            acc += s_s[e] * Vb[(long)s_list[e] * DH_ + dim];
        s_part[tid] = acc;
    }
    __syncthreads();
    if (tid < DH_) {
        const int bb = bh >> 4, h = bh & (H_ - 1);
        float o = (s_part[tid] + s_part[tid + 64]) * s_inv;
        O[((long)(bb * T_ + tq)) * D_ + h * DH_ + tid] = o;
    }
}

// ---------------------------------------------------------------------------
// Launch
// ---------------------------------------------------------------------------
extern "C" void kernel_launch(void* const* d_in, const int* in_sizes, int n_in,
                              void* d_out, int out_size)
{
    const float* x    = (const float*)d_in[0];
    const float* Wq   = (const float*)d_in[1];
    const float* Wk   = (const float*)d_in[2];
    const float* Wv   = (const float*)d_in[3];
    const float* Wo_w = (const float*)d_in[4];
    const float* Wo_b = (const float*)d_in[5];
    float* out = (float*)d_out;

    float *pQ, *pK, *pV, *pS, *pAO;
    cudaGetSymbolAddress((void**)&pQ,  g_Q);
    cudaGetSymbolAddress((void**)&pK,  g_K);
    cudaGetSymbolAddress((void**)&pV,  g_V);
    cudaGetSymbolAddress((void**)&pS,  g_S);
    cudaGetSymbolAddress((void**)&pAO, g_AO);

    const int M = B_ * T_;   // 4096

    // 1) QKV projections (head-split epilogue)
    {
        dim3 grid(D_ / 128, M / 128, 1);
        gemm_abt<EPI_HEADS><<<grid, 256>>>(x, Wq, nullptr, pQ, M, D_, D_, 0, 0, 0);
        gemm_abt<EPI_HEADS><<<grid, 256>>>(x, Wk, nullptr, pK, M, D_, D_, 0, 0, 0);
        gemm_abt<EPI_HEADS><<<grid, 256>>>(x, Wv, nullptr, pV, M, D_, D_, 0, 0, 0);
    }

    // 2) Scores: S[bh] = Q[bh] @ K[bh]^T * 0.125   (batched over 32 bh)
    {
        dim3 grid(T_ / 128, T_ / 128, BH_);
        gemm_abt<EPI_SCALE><<<grid, 256>>>(pQ, pK, nullptr, pS, T_, T_, DH_,
                                           (long)T_ * DH_, (long)T_ * DH_,
                                           (long)T_ * T_);
    }

    // 3) Radix-select top-32 + softmax + sparse AV  -> g_AO [B,T,D]
    {
        dim3 grid(BH_ * T_, 1, 1);   // 65536 blocks
        topk_softmax_av<<<grid, 128>>>(pS, pV, pAO);
    }

    // 4) Output projection with bias -> d_out
    {
        dim3 grid(D_ / 128, M / 128, 1);
        gemm_abt<EPI_BIAS><<<grid, 256>>>(pAO, Wo_w, Wo_b, out, M, D_, D_, 0, 0, 0);
    }
}

// round 5
// speedup vs baseline: 1.6777x; 1.0654x over previous
#include <cuda_runtime.h>
#include <cuda_bf16.h>
#include <cstdint>

// Problem constants
#define B_  2
#define T_  2048
#define D_  1024
#define H_  16
#define DH_ 64
#define TOPK_ 32
#define BH_ (B_*H_)

// Packed fp32x2 FMA (Blackwell): one fma-pipe issue = 2 IEEE fp32 FMAs.
#define FMA_F32X2(d, a, b, c) \
    asm("fma.rn.f32x2 %0, %1, %2, %3;" : "=l"(d) : "l"(a), "l"(b), "l"(c))
#define PACK_DUP_F32X2(out, v) \
    asm("mov.b64 %0, {%1, %1};" : "=l"(out) : "r"(__float_as_uint(v)))
#define UNPACK_F32X2_(lo, hi, in) \
    asm("mov.b64 {%0, %1}, %2;" : "=r"(lo), "=r"(hi) : "l"(in))

// ---------------------------------------------------------------------------
// Scratch (static device globals; no allocation allowed)
// ---------------------------------------------------------------------------
__device__ __align__(16) float g_Q[(size_t)BH_ * T_ * DH_];   // [BH,T,DH]
__device__ __align__(16) float g_K[(size_t)BH_ * T_ * DH_];
__device__ __align__(16) float g_V[(size_t)BH_ * T_ * DH_];
__device__ __align__(16) float g_S[(size_t)BH_ * T_ * T_];    // [BH,T,T] scores
__device__ __align__(16) float g_AO[(size_t)B_ * T_ * D_];    // attn out [B,T,D]

// ---------------------------------------------------------------------------
// Generic C = A @ B^T GEMM, 128x128x16 tile, 256 threads, 8x8 micro-tile,
// packed f32x2 accumulation (8 rows x 4 column-pairs).
// ---------------------------------------------------------------------------
#define EPI_PLAIN 0
#define EPI_BIAS  1
#define EPI_HEADS 2
#define EPI_SCALE 3

template<int EPI>
__global__ __launch_bounds__(256)
void gemm_abt(const float* __restrict__ A, const float* __restrict__ Bm,
              const float* __restrict__ bias, float* __restrict__ C,
              int M, int N, int K,
              long strideA, long strideB, long strideC)
{
    const float* Ab = A + (long)blockIdx.z * strideA;
    const float* Bb = Bm + (long)blockIdx.z * strideB;
    float* Cb = C + (long)blockIdx.z * strideC;

    __shared__ __align__(16) float AsT[16][128];
    __shared__ __align__(16) float BsT[16][128];

    const int tid = threadIdx.x;
    const int tx = tid & 15;
    const int ty = tid >> 4;
    const int m0 = blockIdx.y * 128;
    const int n0 = blockIdx.x * 128;

    unsigned long long acc2[8][4];
#pragma unroll
    for (int i = 0; i < 8; i++)
#pragma unroll
        for (int j = 0; j < 4; j++) acc2[i][j] = 0ull;

    for (int k0 = 0; k0 < K; k0 += 16) {
#pragma unroll
        for (int i = 0; i < 2; i++) {
            int idx  = tid * 2 + i;
            int row  = idx >> 2;
            int col4 = (idx & 3) * 4;
            float4 va = *(const float4*)(Ab + (long)(m0 + row) * K + k0 + col4);
            AsT[col4 + 0][row] = va.x;
            AsT[col4 + 1][row] = va.y;
            AsT[col4 + 2][row] = va.z;
            AsT[col4 + 3][row] = va.w;
            float4 vb = *(const float4*)(Bb + (long)(n0 + row) * K + k0 + col4);
            BsT[col4 + 0][row] = vb.x;
            BsT[col4 + 1][row] = vb.y;
            BsT[col4 + 2][row] = vb.z;
            BsT[col4 + 3][row] = vb.w;
        }
        __syncthreads();
#pragma unroll
        for (int k = 0; k < 16; k++) {
            float a[8];
            *(float4*)&a[0] = *(const float4*)&AsT[k][ty * 8];
            *(float4*)&a[4] = *(const float4*)&AsT[k][ty * 8 + 4];
            // b pairs: 64-bit reinterpretation of consecutive floats (free pack)
            ulonglong2 b01 = *(const ulonglong2*)&BsT[k][tx * 8];
            ulonglong2 b23 = *(const ulonglong2*)&BsT[k][tx * 8 + 4];
            unsigned long long bp0 = b01.x, bp1 = b01.y, bp2 = b23.x, bp3 = b23.y;
#pragma unroll
            for (int i = 0; i < 8; i++) {
                unsigned long long ad;
                PACK_DUP_F32X2(ad, a[i]);
                FMA_F32X2(acc2[i][0], ad, bp0, acc2[i][0]);
                FMA_F32X2(acc2[i][1], ad, bp1, acc2[i][1]);
                FMA_F32X2(acc2[i][2], ad, bp2, acc2[i][2]);
                FMA_F32X2(acc2[i][3], ad, bp3, acc2[i][3]);
            }
        }
        __syncthreads();
    }

#pragma unroll
    for (int i = 0; i < 8; i++) {
        int m = m0 + ty * 8 + i;
#pragma unroll
        for (int jp = 0; jp < 4; jp += 2) {
            int n = n0 + tx * 8 + jp * 2;
            unsigned r0, r1, r2, r3;
            UNPACK_F32X2_(r0, r1, acc2[i][jp]);
            UNPACK_F32X2_(r2, r3, acc2[i][jp + 1]);
            float4 r = make_float4(__uint_as_float(r0), __uint_as_float(r1),
                                   __uint_as_float(r2), __uint_as_float(r3));
            if (EPI == EPI_PLAIN) {
                *(float4*)(Cb + (long)m * N + n) = r;
            } else if (EPI == EPI_BIAS) {
                r.x += bias[n]; r.y += bias[n + 1]; r.z += bias[n + 2]; r.w += bias[n + 3];
                *(float4*)(Cb + (long)m * N + n) = r;
            } else if (EPI == EPI_SCALE) {
                r.x *= 0.125f; r.y *= 0.125f; r.z *= 0.125f; r.w *= 0.125f;
                *(float4*)(Cb + (long)m * N + n) = r;
            } else { // EPI_HEADS: N==1024, write [BH,T,DH]
                int bb = m >> 11, t = m & (T_ - 1);
                int h = n >> 6, inner = n & (DH_ - 1);
                float* dst = Cb + (((long)(bb * H_ + h) * T_ + t) * DH_ + inner);
                *(float4*)dst = r;
            }
        }
    }
}

// ---------------------------------------------------------------------------
// Top-k threshold via 4-level radix select (exact kth largest in monotone
// uint domain), softmax over survivors, sparse P@V.
// One block (128 threads) per query row.
// ---------------------------------------------------------------------------
__device__ __forceinline__ unsigned uencode(float f) {
    unsigned b = __float_as_uint(f);
    return (b & 0x80000000u) ? ~b : (b | 0x80000000u);
}
__device__ __forceinline__ float udecode(unsigned u) {
    unsigned b = (u & 0x80000000u) ? (u & 0x7fffffffu) : ~u;
    return __uint_as_float(b);
}

__global__ __launch_bounds__(128)
void topk_softmax_av(const float* __restrict__ S, const float* __restrict__ V,
                     float* __restrict__ O)
{
    __shared__ int      hist[256];
    __shared__ int      s_list[128];
    __shared__ float    s_s[128];
    __shared__ float    s_part[128];
    __shared__ unsigned s_prefix;
    __shared__ int      s_kp;
    __shared__ int      s_cnt;
    __shared__ float    s_inv;

    const long row = blockIdx.x;            // bh*T + tq
    const int bh = (int)(row >> 11);
    const int tq = (int)(row & (T_ - 1));
    const float* Srow = S + row * T_;
    const int tid = threadIdx.x;

    if (tid == 0) s_cnt = 0;

    unsigned uloc[16];
#pragma unroll
    for (int i = 0; i < 16; i++)
        uloc[i] = uencode(Srow[tid + i * 128]);

    // ---- 4-level radix select ----
    unsigned prefix = 0;
    int kprime = TOPK_;
#pragma unroll
    for (int level = 3; level >= 0; --level) {
        const int sh = level * 8;
        hist[tid] = 0;
        hist[tid + 128] = 0;
        __syncthreads();
        if (level == 3) {
#pragma unroll
            for (int i = 0; i < 16; i++)
                atomicAdd(&hist[uloc[i] >> 24], 1);
        } else {
            const unsigned hip = prefix >> (sh + 8);
#pragma unroll
            for (int i = 0; i < 16; i++) {
                unsigned u = uloc[i];
                if ((u >> (sh + 8)) == hip)
                    atomicAdd(&hist[(u >> sh) & 0xFFu], 1);
            }
        }
        __syncthreads();
        if (tid < 32) {
            const int base = tid * 8;
            int s = 0;
#pragma unroll
            for (int j = 0; j < 8; j++) s += hist[base + j];
            int suf = s;
#pragma unroll
            for (int off = 1; off < 32; off <<= 1) {
                int o = __shfl_down_sync(0xffffffffu, suf, off);
                if (tid + off < 32) suf += o;
            }
            int sufnext = __shfl_down_sync(0xffffffffu, suf, 1);
            if (tid == 31) sufnext = 0;
            unsigned mk = __ballot_sync(0xffffffffu, suf >= kprime);
            int lsel = 31 - __clz(mk);
            if (tid == lsel) {
                int running = sufnext;
                int b = base + 7;
                for (; b >= base; --b) {
                    int h = hist[b];
                    if (running + h >= kprime) break;
                    running += h;
                }
                s_prefix = prefix | ((unsigned)b << sh);
                s_kp = kprime - running;
            }
        }
        __syncthreads();
        prefix = s_prefix;
        kprime = s_kp;
    }
    const unsigned uthr = prefix;

    // ---- compact survivors ----
#pragma unroll
    for (int i = 0; i < 16; i++) {
        unsigned u = uloc[i];
        if (u >= uthr) {
            int pos = atomicAdd(&s_cnt, 1);
            if (pos < 128) {
                s_list[pos] = tid + i * 128;
                s_s[pos] = udecode(u);
            }
        }
    }
    __syncthreads();
    const int cnt = min(s_cnt, 128);

    // ---- softmax over survivors (warp 0) ----
    if (tid < 32) {
        float m = -3.4e38f;
        for (int e = tid; e < cnt; e += 32) m = fmaxf(m, s_s[e]);
#pragma unroll
        for (int off = 16; off; off >>= 1)
            m = fmaxf(m, __shfl_xor_sync(0xffffffffu, m, off));
        float sum = 0.f;
        for (int e = tid; e < cnt; e += 32) {
            float p = __expf(s_s[e] - m);
            s_s[e] = p;
            sum += p;
        }
#pragma unroll
        for (int off = 16; off; off >>= 1)
            sum += __shfl_xor_sync(0xffffffffu, sum, off);
        if (tid == 0) s_inv = 1.f / sum;
    }
    __syncthreads();

    // ---- sparse P @ V ----
    {
        const int dim = tid & 63;
        const int half = tid >> 6;
        const float* Vb = V + (long)bh * T_ * DH_;
        float acc = 0.f;
        for (int e = half; e < cnt; e += 2)
            acc += s_s[e] * Vb[(long)s_list[e] * DH_ + dim];
        s_part[tid] = acc;
    }
    __syncthreads();
    if (tid < DH_) {
        const int bb = bh >> 4, h = bh & (H_ - 1);
        float o = (s_part[tid] + s_part[tid + 64]) * s_inv;
        O[((long)(bb * T_ + tq)) * D_ + h * DH_ + tid] = o;
    }
}

// ---------------------------------------------------------------------------
// Launch
// ---------------------------------------------------------------------------
extern "C" void kernel_launch(void* const* d_in, const int* in_sizes, int n_in,
                              void* d_out, int out_size)
{
    const float* x    = (const float*)d_in[0];
    const float* Wq   = (const float*)d_in[1];
    const float* Wk   = (const float*)d_in[2];
    const float* Wv   = (const float*)d_in[3];
    const float* Wo_w = (const float*)d_in[4];
    const float* Wo_b = (const float*)d_in[5];
    float* out = (float*)d_out;

    float *pQ, *pK, *pV, *pS, *pAO;
    cudaGetSymbolAddress((void**)&pQ,  g_Q);
    cudaGetSymbolAddress((void**)&pK,  g_K);
    cudaGetSymbolAddress((void**)&pV,  g_V);
    cudaGetSymbolAddress((void**)&pS,  g_S);
    cudaGetSymbolAddress((void**)&pAO, g_AO);

    const int M = B_ * T_;   // 4096

    // 1) QKV projections (head-split epilogue)
    {
        dim3 grid(D_ / 128, M / 128, 1);
        gemm_abt<EPI_HEADS><<<grid, 256>>>(x, Wq, nullptr, pQ, M, D_, D_, 0, 0, 0);
        gemm_abt<EPI_HEADS><<<grid, 256>>>(x, Wk, nullptr, pK, M, D_, D_, 0, 0, 0);
        gemm_abt<EPI_HEADS><<<grid, 256>>>(x, Wv, nullptr, pV, M, D_, D_, 0, 0, 0);
    }

    // 2) Scores: S[bh] = Q[bh] @ K[bh]^T * 0.125   (batched over 32 bh)
    {
        dim3 grid(T_ / 128, T_ / 128, BH_);
        gemm_abt<EPI_SCALE><<<grid, 256>>>(pQ, pK, nullptr, pS, T_, T_, DH_,
                                           (long)T_ * DH_, (long)T_ * DH_,
                                           (long)T_ * T_);
    }

    // 3) Radix-select top-32 + softmax + sparse AV  -> g_AO [B,T,D]
    {
        dim3 grid(BH_ * T_, 1, 1);   // 65536 blocks
        topk_softmax_av<<<grid, 128>>>(pS, pV, pAO);
    }

    // 4) Output projection with bias -> d_out
    {
        dim3 grid(D_ / 128, M / 128, 1);
        gemm_abt<EPI_BIAS><<<grid, 256>>>(pAO, Wo_w, Wo_b, out, M, D_, D_, 0, 0, 0);
    }
}

// round 8
// speedup vs baseline: 1.9577x; 1.1669x over previous
#include <cuda_runtime.h>
#include <cuda_bf16.h>
#include <cstdint>

// Problem constants
#define B_  2
#define T_  2048
#define D_  1024
#define H_  16
#define DH_ 64
#define TOPK_ 32
#define BH_ (B_*H_)

// Packed fp32x2 FMA
#define FMA_F32X2(d, a, b, c) \
    asm("fma.rn.f32x2 %0, %1, %2, %3;" : "=l"(d) : "l"(a), "l"(b), "l"(c))
#define PACK_DUP_F32X2(out, v) \
    asm("mov.b64 %0, {%1, %1};" : "=l"(out) : "r"(__float_as_uint(v)))
#define UNPACK_F32X2_(lo, hi, in) \
    asm("mov.b64 {%0, %1}, %2;" : "=r"(lo), "=r"(hi) : "l"(in))

__device__ __forceinline__ uint32_t smem_u32(const void* p) {
    uint32_t a;
    asm("{ .reg .u64 t; cvta.to.shared.u64 t, %1; cvt.u32.u64 %0, t; }" : "=r"(a) : "l"(p));
    return a;
}
__device__ __forceinline__ void ldsm_x4(unsigned r[4], uint32_t addr) {
    asm volatile("ldmatrix.sync.aligned.m8n8.x4.shared.b16 {%0,%1,%2,%3}, [%4];"
        : "=r"(r[0]), "=r"(r[1]), "=r"(r[2]), "=r"(r[3]) : "r"(addr));
}
__device__ __forceinline__ void ldsm_x2(unsigned r[2], uint32_t addr) {
    asm volatile("ldmatrix.sync.aligned.m8n8.x2.shared.b16 {%0,%1}, [%2];"
        : "=r"(r[0]), "=r"(r[1]) : "r"(addr));
}
__device__ __forceinline__ void mma_bf16(float d[4], const unsigned a[4], const unsigned b[2]) {
    asm volatile("mma.sync.aligned.m16n8k16.row.col.f32.bf16.bf16.f32 "
        "{%0,%1,%2,%3}, {%4,%5,%6,%7}, {%8,%9}, {%0,%1,%2,%3};"
        : "+f"(d[0]), "+f"(d[1]), "+f"(d[2]), "+f"(d[3])
        : "r"(a[0]), "r"(a[1]), "r"(a[2]), "r"(a[3]), "r"(b[0]), "r"(b[1]));
}
// swizzled byte offset of 16B group g in row r (row = 64B = 32 bf16)
__device__ __forceinline__ uint32_t stoff(int r, int g) {
    return (uint32_t)(r * 64 + ((g ^ ((r >> 1) & 3)) << 4));
}

// ---------------------------------------------------------------------------
// Scratch
// ---------------------------------------------------------------------------
__device__ __align__(16) float g_Q[(size_t)BH_ * T_ * DH_];
__device__ __align__(16) float g_K[(size_t)BH_ * T_ * DH_];
__device__ __align__(16) float g_V[(size_t)BH_ * T_ * DH_];
__device__ __align__(16) float g_S[(size_t)BH_ * T_ * T_];
__device__ __align__(16) float g_AO[(size_t)B_ * T_ * D_];
__device__ __align__(16) __nv_bfloat16 g_Xs [(size_t)4096 * 3072];  // (h,h,l)
__device__ __align__(16) __nv_bfloat16 g_AOs[(size_t)4096 * 3072];  // (h,h,l)
__device__ __align__(16) __nv_bfloat16 g_Wvs[(size_t)1024 * 3072];  // (h,l,h)
__device__ __align__(16) __nv_bfloat16 g_Wos[(size_t)1024 * 3072];  // (h,l,h)

// ---------------------------------------------------------------------------
// Split: fp32 [R,1024] -> bf16 [R,3072]; AHL=1 (h,h,l), AHL=0 (h,l,h)
// ---------------------------------------------------------------------------
template<int AHL>
__global__ __launch_bounds__(256)
void split_bf16(const float* __restrict__ in, __nv_bfloat16* __restrict__ outp)
{
    const int idx = blockIdx.x * 256 + threadIdx.x;
    const int r = idx >> 8;
    const int c = (idx & 255) * 4;
    float4 v = *(const float4*)(in + (size_t)r * 1024 + c);
    __nv_bfloat162 h01 = __floats2bfloat162_rn(v.x, v.y);
    __nv_bfloat162 h23 = __floats2bfloat162_rn(v.z, v.w);
    float lx = v.x - __bfloat162float(h01.x);
    float ly = v.y - __bfloat162float(h01.y);
    float lz = v.z - __bfloat162float(h23.x);
    float lw = v.w - __bfloat162float(h23.y);
    __nv_bfloat162 l01 = __floats2bfloat162_rn(lx, ly);
    __nv_bfloat162 l23 = __floats2bfloat162_rn(lz, lw);
    __nv_bfloat162* o0 = (__nv_bfloat162*)(outp + (size_t)r * 3072 + c);
    __nv_bfloat162* o1 = (__nv_bfloat162*)(outp + (size_t)r * 3072 + 1024 + c);
    __nv_bfloat162* o2 = (__nv_bfloat162*)(outp + (size_t)r * 3072 + 2048 + c);
    o0[0] = h01; o0[1] = h23;
    if (AHL) { o1[0] = h01; o1[1] = h23; o2[0] = l01; o2[1] = l23; }
    else     { o1[0] = l01; o1[1] = l23; o2[0] = h01; o2[1] = h23; }
}

// ---------------------------------------------------------------------------
// HMMA bf16 GEMM: C[M,1024] = A'[M,3072] @ B'[1024,3072]^T, fp32 accum.
// 128x128 CTA tile, 8 warps (2x4), 64x32 warp tile, m16n8k16 mma.sync.
// EPI 0: head-split write [BH,T,DH];  EPI 1: +bias plain [M,1024]
// ---------------------------------------------------------------------------
template<int EPI>
__global__ __launch_bounds__(256, 2)
void gemm_bf16_mma(const __nv_bfloat16* __restrict__ A,
                   const __nv_bfloat16* __restrict__ Bm,
                   const float* __restrict__ bias, float* __restrict__ C)
{
    constexpr int KT = 3072;
    constexpr int KC = 32;              // bf16 per chunk (64B rows)
    constexpr int NC = KT / KC;         // 96 chunks
    constexpr uint32_t TILE = 128 * 64; // 8192 B per operand tile
    __shared__ __align__(128) char sm[2][2][TILE];   // [buf][A/B]

    const int tid = threadIdx.x, lane = tid & 31, wid = tid >> 5;
    const int wr = wid >> 2, wc = wid & 3;
    const int m0 = blockIdx.y * 128, n0 = blockIdx.x * 128;
    const uint32_t sbase = smem_u32(&sm[0][0][0]);

    float acc[4][4][4];
#pragma unroll
    for (int mb = 0; mb < 4; mb++)
#pragma unroll
        for (int nb = 0; nb < 4; nb++)
#pragma unroll
            for (int e = 0; e < 4; e++) acc[mb][nb][e] = 0.f;

    // ldmatrix lane addressing offsets
    const int aRow = (lane & 15), aG = (lane >> 4) & 1;     // x4
    const int bRow = (lane & 7),  bG = (lane >> 3) & 1;     // x2

    // preload chunk 0 -> buf 0
#pragma unroll
    for (int j = 0; j < 2; j++) {
        int p = tid + j * 256;          // 0..511
        int r = p >> 2, g = p & 3;
        *(uint4*)(&sm[0][0][0] + stoff(r, g)) = *(const uint4*)(A  + (size_t)(m0 + r) * KT + g * 8);
        *(uint4*)(&sm[0][1][0] + stoff(r, g)) = *(const uint4*)(Bm + (size_t)(n0 + r) * KT + g * 8);
    }
    __syncthreads();

    for (int c = 0; c < NC; c++) {
        const int buf = c & 1;
        // prefetch next chunk into other buffer
        if (c + 1 < NC) {
            const int ks = (c + 1) * KC;
            const int nb_ = buf ^ 1;
#pragma unroll
            for (int j = 0; j < 2; j++) {
                int p = tid + j * 256;
                int r = p >> 2, g = p & 3;
                *(uint4*)(&sm[nb_][0][0] + stoff(r, g)) = *(const uint4*)(A  + (size_t)(m0 + r) * KT + ks + g * 8);
                *(uint4*)(&sm[nb_][1][0] + stoff(r, g)) = *(const uint4*)(Bm + (size_t)(n0 + r) * KT + ks + g * 8);
            }
        }
        // compute on buf
        const uint32_t Ab = sbase + (uint32_t)buf * (2 * TILE);
        const uint32_t Bb = Ab + TILE;
#pragma unroll
        for (int s16 = 0; s16 < 2; s16++) {
            unsigned bf[4][2];
#pragma unroll
            for (int nb = 0; nb < 4; nb++) {
                int r = 32 * wc + 8 * nb + bRow;
                ldsm_x2(bf[nb], Bb + stoff(r, s16 * 2 + bG));
            }
#pragma unroll
            for (int mb = 0; mb < 4; mb++) {
                unsigned af[4];
                int r = 64 * wr + 16 * mb + aRow;
                ldsm_x4(af, Ab + stoff(r, s16 * 2 + aG));
#pragma unroll
                for (int nb = 0; nb < 4; nb++)
                    mma_bf16(acc[mb][nb], af, bf[nb]);
            }
        }
        __syncthreads();
    }

    // epilogue
#pragma unroll
    for (int mb = 0; mb < 4; mb++) {
        const int mlo = m0 + 64 * wr + 16 * mb + (lane >> 2);
#pragma unroll
        for (int nb = 0; nb < 4; nb++) {
            const int n = n0 + 32 * wc + 8 * nb + (lane & 3) * 2;
            float2 lo = make_float2(acc[mb][nb][0], acc[mb][nb][1]);
            float2 hi = make_float2(acc[mb][nb][2], acc[mb][nb][3]);
            if (EPI == 1) {
                float bx = bias[n], by = bias[n + 1];
                lo.x += bx; lo.y += by; hi.x += bx; hi.y += by;
                *(float2*)(C + (size_t)mlo * 1024 + n) = lo;
                *(float2*)(C + (size_t)(mlo + 8) * 1024 + n) = hi;
            } else {
                const int h = n >> 6, inner = n & 63;
                const int bb0 = mlo >> 11, t0v = mlo & (T_ - 1);
                const int bb1 = (mlo + 8) >> 11, t1v = (mlo + 8) & (T_ - 1);
                *(float2*)(C + (((size_t)(bb0 * H_ + h) * T_ + t0v) * DH_ + inner)) = lo;
                *(float2*)(C + (((size_t)(bb1 * H_ + h) * T_ + t1v) * DH_ + inner)) = hi;
            }
        }
    }
}

// ---------------------------------------------------------------------------
// SIMT FFMA2 GEMM (Q, K projections + scores)
// ---------------------------------------------------------------------------
#define EPI_HEADS 2
#define EPI_SCALE 3

template<int EPI>
__global__ __launch_bounds__(256)
void gemm_abt(const float* __restrict__ A, const float* __restrict__ Bm,
              float* __restrict__ C, int M, int N, int K,
              long strideA, long strideB, long strideC)
{
    const float* Ab = A + (long)blockIdx.z * strideA;
    const float* Bb = Bm + (long)blockIdx.z * strideB;
    float* Cb = C + (long)blockIdx.z * strideC;

    __shared__ __align__(16) float AsT[16][128];
    __shared__ __align__(16) float BsT[16][128];

    const int tid = threadIdx.x;
    const int tx = tid & 15;
    const int ty = tid >> 4;
    const int m0 = blockIdx.y * 128;
    const int n0 = blockIdx.x * 128;

    unsigned long long acc2[8][4];
#pragma unroll
    for (int i = 0; i < 8; i++)
#pragma unroll
        for (int j = 0; j < 4; j++) acc2[i][j] = 0ull;

    for (int k0 = 0; k0 < K; k0 += 16) {
#pragma unroll
        for (int i = 0; i < 2; i++) {
            int idx  = tid * 2 + i;
            int row  = idx >> 2;
            int col4 = (idx & 3) * 4;
            float4 va = *(const float4*)(Ab + (long)(m0 + row) * K + k0 + col4);
            AsT[col4 + 0][row] = va.x;
            AsT[col4 + 1][row] = va.y;
            AsT[col4 + 2][row] = va.z;
            AsT[col4 + 3][row] = va.w;
            float4 vb = *(const float4*)(Bb + (long)(n0 + row) * K + k0 + col4);
            BsT[col4 + 0][row] = vb.x;
            BsT[col4 + 1][row] = vb.y;
            BsT[col4 + 2][row] = vb.z;
            BsT[col4 + 3][row] = vb.w;
        }
        __syncthreads();
#pragma unroll
        for (int k = 0; k < 16; k++) {
            float a[8];
            *(float4*)&a[0] = *(const float4*)&AsT[k][ty * 8];
            *(float4*)&a[4] = *(const float4*)&AsT[k][ty * 8 + 4];
            ulonglong2 b01 = *(const ulonglong2*)&BsT[k][tx * 8];
            ulonglong2 b23 = *(const ulonglong2*)&BsT[k][tx * 8 + 4];
#pragma unroll
            for (int i = 0; i < 8; i++) {
                unsigned long long ad;
                PACK_DUP_F32X2(ad, a[i]);
                FMA_F32X2(acc2[i][0], ad, b01.x, acc2[i][0]);
                FMA_F32X2(acc2[i][1], ad, b01.y, acc2[i][1]);
                FMA_F32X2(acc2[i][2], ad, b23.x, acc2[i][2]);
                FMA_F32X2(acc2[i][3], ad, b23.y, acc2[i][3]);
            }
        }
        __syncthreads();
    }

#pragma unroll
    for (int i = 0; i < 8; i++) {
        int m = m0 + ty * 8 + i;
#pragma unroll
        for (int jp = 0; jp < 4; jp += 2) {
            int n = n0 + tx * 8 + jp * 2;
            unsigned r0, r1, r2, r3;
            UNPACK_F32X2_(r0, r1, acc2[i][jp]);
            UNPACK_F32X2_(r2, r3, acc2[i][jp + 1]);
            float4 r = make_float4(__uint_as_float(r0), __uint_as_float(r1),
                                   __uint_as_float(r2), __uint_as_float(r3));
            if (EPI == EPI_SCALE) {
                r.x *= 0.125f; r.y *= 0.125f; r.z *= 0.125f; r.w *= 0.125f;
                *(float4*)(Cb + (long)m * N + n) = r;
            } else {
                int bb = m >> 11, t = m & (T_ - 1);
                int h = n >> 6, inner = n & (DH_ - 1);
                float* dst = Cb + (((long)(bb * H_ + h) * T_ + t) * DH_ + inner);
                *(float4*)dst = r;
            }
        }
    }
}

// ---------------------------------------------------------------------------
// Top-k radix select + softmax + sparse AV
// ---------------------------------------------------------------------------
__device__ __forceinline__ unsigned uencode(float f) {
    unsigned b = __float_as_uint(f);
    return (b & 0x80000000u) ? ~b : (b | 0x80000000u);
}
__device__ __forceinline__ float udecode(unsigned u) {
    unsigned b = (u & 0x80000000u) ? (u & 0x7fffffffu) : ~u;
    return __uint_as_float(b);
}

__global__ __launch_bounds__(128)
void topk_softmax_av(const float* __restrict__ S, const float* __restrict__ V,
                     float* __restrict__ O)
{
    __shared__ int      hist[256];
    __shared__ int      s_list[128];
    __shared__ float    s_s[128];
    __shared__ float    s_part[128];
    __shared__ unsigned s_prefix;
    __shared__ int      s_kp;
    __shared__ int      s_cnt;
    __shared__ float    s_inv;

    const long row = blockIdx.x;
    const int bh = (int)(row >> 11);
    const int tq = (int)(row & (T_ - 1));
    const float* Srow = S + row * T_;
    const int tid = threadIdx.x;

    if (tid == 0) s_cnt = 0;

    unsigned uloc[16];
#pragma unroll
    for (int i = 0; i < 16; i++)
        uloc[i] = uencode(Srow[tid + i * 128]);

    unsigned prefix = 0;
    int kprime = TOPK_;
#pragma unroll
    for (int level = 3; level >= 0; --level) {
        const int sh = level * 8;
        hist[tid] = 0;
        hist[tid + 128] = 0;
        __syncthreads();
        if (level == 3) {
#pragma unroll
            for (int i = 0; i < 16; i++)
                atomicAdd(&hist[uloc[i] >> 24], 1);
        } else {
            const unsigned hip = prefix >> (sh + 8);
#pragma unroll
            for (int i = 0; i < 16; i++) {
                unsigned u = uloc[i];
                if ((u >> (sh + 8)) == hip)
                    atomicAdd(&hist[(u >> sh) & 0xFFu], 1);
            }
        }
        __syncthreads();
        if (tid < 32) {
            const int base = tid * 8;
            int s = 0;
#pragma unroll
            for (int j = 0; j < 8; j++) s += hist[base + j];
            int suf = s;
#pragma unroll
            for (int off = 1; off < 32; off <<= 1) {
                int o = __shfl_down_sync(0xffffffffu, suf, off);
                if (tid + off < 32) suf += o;
            }
            int sufnext = __shfl_down_sync(0xffffffffu, suf, 1);
            if (tid == 31) sufnext = 0;
            unsigned mk = __ballot_sync(0xffffffffu, suf >= kprime);
            int lsel = 31 - __clz(mk);
            if (tid == lsel) {
                int running = sufnext;
                int b = base + 7;
                for (; b >= base; --b) {
                    int h = hist[b];
                    if (running + h >= kprime) break;
                    running += h;
                }
                s_prefix = prefix | ((unsigned)b << sh);
                s_kp = kprime - running;
            }
        }
        __syncthreads();
        prefix = s_prefix;
        kprime = s_kp;
    }
    const unsigned uthr = prefix;

#pragma unroll
    for (int i = 0; i < 16; i++) {
        unsigned u = uloc[i];
        if (u >= uthr) {
            int pos = atomicAdd(&s_cnt, 1);
            if (pos < 128) {
                s_list[pos] = tid + i * 128;
                s_s[pos] = udecode(u);
            }
        }
    }
    __syncthreads();
    const int cnt = min(s_cnt, 128);

    if (tid < 32) {
        float m = -3.4e38f;
        for (int e = tid; e < cnt; e += 32) m = fmaxf(m, s_s[e]);
#pragma unroll
        for (int off = 16; off; off >>= 1)
            m = fmaxf(m, __shfl_xor_sync(0xffffffffu, m, off));
        float sum = 0.f;
        for (int e = tid; e < cnt; e += 32) {
            float p = __expf(s_s[e] - m);
            s_s[e] = p;
            sum += p;
        }
#pragma unroll
        for (int off = 16; off; off >>= 1)
            sum += __shfl_xor_sync(0xffffffffu, sum, off);
        if (tid == 0) s_inv = 1.f / sum;
    }
    __syncthreads();

    {
        const int dim = tid & 63;
        const int half = tid >> 6;
        const float* Vb = V + (long)bh * T_ * DH_;
        float acc = 0.f;
        for (int e = half; e < cnt; e += 2)
            acc += s_s[e] * Vb[(long)s_list[e] * DH_ + dim];
        s_part[tid] = acc;
    }
    __syncthreads();
    if (tid < DH_) {
        const int bb = bh >> 4, h = bh & (H_ - 1);
        float o = (s_part[tid] + s_part[tid + 64]) * s_inv;
        O[((long)(bb * T_ + tq)) * D_ + h * DH_ + tid] = o;
    }
}

// ---------------------------------------------------------------------------
// Launch
// ---------------------------------------------------------------------------
extern "C" void kernel_launch(void* const* d_in, const int* in_sizes, int n_in,
                              void* d_out, int out_size)
{
    const float* x    = (const float*)d_in[0];
    const float* Wq   = (const float*)d_in[1];
    const float* Wk   = (const float*)d_in[2];
    const float* Wv   = (const float*)d_in[3];
    const float* Wo_w = (const float*)d_in[4];
    const float* Wo_b = (const float*)d_in[5];
    float* out = (float*)d_out;

    float *pQ, *pK, *pV, *pS, *pAO;
    __nv_bfloat16 *pXs, *pAOs, *pWvs, *pWos;
    cudaGetSymbolAddress((void**)&pQ,  g_Q);
    cudaGetSymbolAddress((void**)&pK,  g_K);
    cudaGetSymbolAddress((void**)&pV,  g_V);
    cudaGetSymbolAddress((void**)&pS,  g_S);
    cudaGetSymbolAddress((void**)&pAO, g_AO);
    cudaGetSymbolAddress((void**)&pXs,  g_Xs);
    cudaGetSymbolAddress((void**)&pAOs, g_AOs);
    cudaGetSymbolAddress((void**)&pWvs, g_Wvs);
    cudaGetSymbolAddress((void**)&pWos, g_Wos);

    const int M = B_ * T_;   // 4096

    // 0) bf16 splits for tensor-core operands
    split_bf16<1><<<4096, 256>>>(x, pXs);
    split_bf16<0><<<1024, 256>>>(Wv, pWvs);
    split_bf16<0><<<1024, 256>>>(Wo_w, pWos);

    // 1) Q, K projections (SIMT fp32, selection-critical)
    {
        dim3 grid(D_ / 128, M / 128, 1);
        gemm_abt<EPI_HEADS><<<grid, 256>>>(x, Wq, pQ, M, D_, D_, 0, 0, 0);
        gemm_abt<EPI_HEADS><<<grid, 256>>>(x, Wk, pK, M, D_, D_, 0, 0, 0);
    }
    // 1b) V projection (HMMA tensor cores, head-split epilogue)
    {
        dim3 grid(D_ / 128, M / 128, 1);
        gemm_bf16_mma<0><<<grid, 256>>>(pXs, pWvs, nullptr, pV);
    }

    // 2) Scores (SIMT fp32, selection-critical)
    {
        dim3 grid(T_ / 128, T_ / 128, BH_);
        gemm_abt<EPI_SCALE><<<grid, 256>>>(pQ, pK, pS, T_, T_, DH_,
                                           (long)T_ * DH_, (long)T_ * DH_,
                                           (long)T_ * T_);
    }

    // 3) Radix-select top-32 + softmax + sparse AV
    topk_softmax_av<<<BH_ * T_, 128>>>(pS, pV, pAO);

    // 4) Output projection (HMMA tensor cores + bias)
    split_bf16<1><<<4096, 256>>>(pAO, pAOs);
    {
        dim3 grid(D_ / 128, M / 128, 1);
        gemm_bf16_mma<1><<<grid, 256>>>(pAOs, pWos, Wo_b, out);
    }
}